// round 6
// baseline (speedup 1.0000x reference)
#include <cuda_runtime.h>
#include <cstdint>

#define NN 50000
#define FIN 512
#define H1C 64     // 8 heads * 8
#define H2C 40     // 1 head * 40
#define EMAX 1700000

// ---------------- scratch (device globals; no allocation allowed) -------------
__device__ int   g_src[EMAX + NN];
__device__ int   g_dst[EMAX + NN];
__device__ float g_h1[NN * H1C];    // x @ W1
__device__ float g_as1[NN * 8];     // a_src layer1
__device__ float g_ad1[NN * 8];     // a_dst layer1
__device__ float g_den1[NN * 8];    // softmax denom layer1
__device__ float g_out1[NN * H1C];  // layer1 aggregated output
__device__ float g_h2[NN * H2C];    // relu(out1) @ W2
__device__ float g_as2[NN];
__device__ float g_ad2[NN];
__device__ float g_den2[NN];

// vector reduction to global (sm_90+)
__device__ __forceinline__ void red_add_v4(float* addr, float x, float y, float z, float w) {
    asm volatile("red.global.add.v4.f32 [%0], {%1,%2,%3,%4};"
                 :: "l"(addr), "f"(x), "f"(y), "f"(z), "f"(w) : "memory");
}

__device__ __forceinline__ float lrelu_exp(float e) {
    e = (e < 0.f) ? 0.2f * e : e;
    return __expf(e);
}

// ---------------- decode edge index (int32 OR int64) + append self loops ------
// If stored int64 (little-endian), odd 32-bit words are the high halves = 0
// for all values in [0, 50000). Random node ids make 4 consecutive zero-high
// words astronomically unlikely under int32 interpretation.
__global__ void k_decode(const int* __restrict__ w, int E) {
    bool is64 = (w[1] == 0 && w[3] == 0 && w[5] == 0 && w[7] == 0);
    int i = blockIdx.x * blockDim.x + threadIdx.x;
    int ET = E + NN;
    if (i >= ET) return;
    if (i >= E) {               // self loop
        g_src[i] = i - E;
        g_dst[i] = i - E;
    } else if (is64) {
        const long long* e64 = (const long long*)w;
        g_src[i] = (int)e64[i];
        g_dst[i] = (int)e64[E + i];
    } else {
        g_src[i] = w[i];
        g_dst[i] = w[E + i];
    }
}

// ---------------- init: zero accumulators + final output ----------------------
__global__ void k_zero(float* out) {
    int i = blockIdx.x * blockDim.x + threadIdx.x;
    int stride = gridDim.x * blockDim.x;
    for (int j = i; j < NN * H1C; j += stride) g_out1[j] = 0.f;
    for (int j = i; j < NN * 8;   j += stride) g_den1[j] = 0.f;
    for (int j = i; j < NN;       j += stride) g_den2[j] = 0.f;
    for (int j = i; j < NN * H2C; j += stride) out[j] = 0.f;
}

// ---------------- GEMM1: h1 = x[50000,512] @ W1[512,64] -----------------------
// BM=64, BN=64, BK=16, 256 threads, 4x4 per thread
__global__ void k_gemm1(const float* __restrict__ x, const float* __restrict__ W) {
    __shared__ float As[16][64];   // [k][m]
    __shared__ float Bs[16][64];   // [k][n]
    int t = threadIdx.x;
    int m0 = blockIdx.x * 64;
    int tx = t & 15, ty = t >> 4;
    int lrow = t >> 2, lq = t & 3;   // A-load: row, quarter
    int krow = t >> 4, kq = t & 15;  // B-load: k-row, quarter
    float acc[4][4] = {};
    for (int k0 = 0; k0 < FIN; k0 += 16) {
        float4 av = make_float4(0.f, 0.f, 0.f, 0.f);
        int gm = m0 + lrow;
        if (gm < NN) av = *(const float4*)(x + (size_t)gm * FIN + k0 + 4 * lq);
        As[4 * lq + 0][lrow] = av.x;
        As[4 * lq + 1][lrow] = av.y;
        As[4 * lq + 2][lrow] = av.z;
        As[4 * lq + 3][lrow] = av.w;
        *(float4*)&Bs[krow][4 * kq] = *(const float4*)(W + (size_t)(k0 + krow) * 64 + 4 * kq);
        __syncthreads();
#pragma unroll
        for (int k = 0; k < 16; k++) {
            float4 a = *(const float4*)&As[k][ty * 4];
            float4 b = *(const float4*)&Bs[k][tx * 4];
            acc[0][0] += a.x * b.x; acc[0][1] += a.x * b.y; acc[0][2] += a.x * b.z; acc[0][3] += a.x * b.w;
            acc[1][0] += a.y * b.x; acc[1][1] += a.y * b.y; acc[1][2] += a.y * b.z; acc[1][3] += a.y * b.w;
            acc[2][0] += a.z * b.x; acc[2][1] += a.z * b.y; acc[2][2] += a.z * b.z; acc[2][3] += a.z * b.w;
            acc[3][0] += a.w * b.x; acc[3][1] += a.w * b.y; acc[3][2] += a.w * b.z; acc[3][3] += a.w * b.w;
        }
        __syncthreads();
    }
#pragma unroll
    for (int i = 0; i < 4; i++) {
        int gm = m0 + ty * 4 + i;
        if (gm < NN) {
            float4 v = make_float4(acc[i][0], acc[i][1], acc[i][2], acc[i][3]);
            *(float4*)(g_h1 + (size_t)gm * 64 + tx * 4) = v;
        }
    }
}

// ---------------- per-node attention coefficients (layer1) --------------------
__global__ void k_a1(const float* __restrict__ attS, const float* __restrict__ attD) {
    int n = blockIdx.x * blockDim.x + threadIdx.x;
    if (n >= NN) return;
    const float* hr = g_h1 + (size_t)n * 64;
#pragma unroll
    for (int h = 0; h < 8; h++) {
        float s = 0.f, d = 0.f;
#pragma unroll
        for (int c = 0; c < 8; c++) {
            float v = hr[h * 8 + c];
            s += v * __ldg(attS + h * 8 + c);
            d += v * __ldg(attD + h * 8 + c);
        }
        g_as1[n * 8 + h] = s;
        g_ad1[n * 8 + h] = d;
    }
}

// ---------------- layer1 edge pass A: softmax denominators --------------------
__global__ void k_e1den(int ET) {
    int e = blockIdx.x * blockDim.x + threadIdx.x;
    if (e >= ET) return;
    int s = g_src[e], d = g_dst[e];
    float4 as0 = *(const float4*)(g_as1 + s * 8);
    float4 as1 = *(const float4*)(g_as1 + s * 8 + 4);
    float4 ad0 = *(const float4*)(g_ad1 + d * 8);
    float4 ad1 = *(const float4*)(g_ad1 + d * 8 + 4);
    red_add_v4(g_den1 + d * 8,
               lrelu_exp(as0.x + ad0.x), lrelu_exp(as0.y + ad0.y),
               lrelu_exp(as0.z + ad0.z), lrelu_exp(as0.w + ad0.w));
    red_add_v4(g_den1 + d * 8 + 4,
               lrelu_exp(as1.x + ad1.x), lrelu_exp(as1.y + ad1.y),
               lrelu_exp(as1.z + ad1.z), lrelu_exp(as1.w + ad1.w));
}

// ---------------- layer1 edge pass B: weighted scatter ------------------------
// 16 lanes per edge, lane l -> head l>>1, float4 chunk l
__global__ void k_e1scat(int ET) {
    int gt = blockIdx.x * blockDim.x + threadIdx.x;
    int e = gt >> 4;
    int l = gt & 15;
    if (e >= ET) return;
    int s = g_src[e], d = g_dst[e];
    int h = l >> 1;
    float ex = lrelu_exp(g_as1[s * 8 + h] + g_ad1[d * 8 + h]);
    float alpha = ex / (g_den1[d * 8 + h] + 1e-16f);
    float4 hv = *(const float4*)(g_h1 + (size_t)s * 64 + l * 4);
    red_add_v4(g_out1 + (size_t)d * 64 + l * 4,
               alpha * hv.x, alpha * hv.y, alpha * hv.z, alpha * hv.w);
}

// ---------------- layer2 node phase: relu(out1+b1) @ W2, a2 -------------------
__global__ void k_l2(const float* __restrict__ W2, const float* __restrict__ b1,
                     const float* __restrict__ aS2, const float* __restrict__ aD2) {
    __shared__ float Wsm[64 * 40];
    __shared__ float b1s[64], aSs[40], aDs[40];
    int t = threadIdx.x;
    for (int i = t; i < 64 * 40; i += 128) Wsm[i] = W2[i];
    if (t < 64) b1s[t] = b1[t];
    if (t < 40) { aSs[t] = aS2[t]; aDs[t] = aD2[t]; }
    __syncthreads();
    int n = blockIdx.x * 128 + t;
    if (n >= NN) return;
    float acc[40] = {};
    const float* r = g_out1 + (size_t)n * 64;
#pragma unroll
    for (int k4 = 0; k4 < 16; k4++) {
        float4 v = *(const float4*)(r + k4 * 4);
        v.x = fmaxf(v.x + b1s[4 * k4 + 0], 0.f);
        v.y = fmaxf(v.y + b1s[4 * k4 + 1], 0.f);
        v.z = fmaxf(v.z + b1s[4 * k4 + 2], 0.f);
        v.w = fmaxf(v.w + b1s[4 * k4 + 3], 0.f);
#pragma unroll
        for (int c = 0; c < 40; c++) {
            acc[c] += v.x * Wsm[(4 * k4 + 0) * 40 + c]
                    + v.y * Wsm[(4 * k4 + 1) * 40 + c]
                    + v.z * Wsm[(4 * k4 + 2) * 40 + c]
                    + v.w * Wsm[(4 * k4 + 3) * 40 + c];
        }
    }
    float s2 = 0.f, d2 = 0.f;
#pragma unroll
    for (int c = 0; c < 40; c++) {
        g_h2[(size_t)n * 40 + c] = acc[c];
        s2 += acc[c] * aSs[c];
        d2 += acc[c] * aDs[c];
    }
    g_as2[n] = s2;
    g_ad2[n] = d2;
}

// ---------------- layer2 edge pass A ------------------------------------------
__global__ void k_e2den(int ET) {
    int e = blockIdx.x * blockDim.x + threadIdx.x;
    if (e >= ET) return;
    int s = g_src[e], d = g_dst[e];
    float ex = lrelu_exp(g_as2[s] + g_ad2[d]);
    atomicAdd(g_den2 + d, ex);
}

// ---------------- layer2 edge pass B: scatter into d_out ----------------------
// 16 lanes per edge, lanes 0..9 each handle one float4 of the 40-wide row
__global__ void k_e2scat(int ET, float* __restrict__ out) {
    int gt = blockIdx.x * blockDim.x + threadIdx.x;
    int e = gt >> 4;
    int l = gt & 15;
    if (e >= ET || l >= 10) return;
    int s = g_src[e], d = g_dst[e];
    float ex = lrelu_exp(g_as2[s] + g_ad2[d]);
    float alpha = ex / (g_den2[d] + 1e-16f);
    float4 hv = *(const float4*)(g_h2 + (size_t)s * 40 + l * 4);
    red_add_v4(out + (size_t)d * 40 + l * 4,
               alpha * hv.x, alpha * hv.y, alpha * hv.z, alpha * hv.w);
}

// ---------------- bias + log_softmax (warp per node, 40 cols) -----------------
__global__ void k_lsm(float* __restrict__ out, const float* __restrict__ b2) {
    int gt = blockIdx.x * blockDim.x + threadIdx.x;
    int node = gt >> 5;
    int lane = gt & 31;
    if (node >= NN) return;
    float* row = out + (size_t)node * 40;
    float v0 = row[lane] + __ldg(b2 + lane);
    float v1 = (lane < 8) ? (row[lane + 32] + __ldg(b2 + lane + 32)) : -3.4e38f;
    float m = fmaxf(v0, v1);
#pragma unroll
    for (int o = 16; o > 0; o >>= 1) m = fmaxf(m, __shfl_xor_sync(0xffffffffu, m, o));
    float sum = __expf(v0 - m) + ((lane < 8) ? __expf(v1 - m) : 0.f);
#pragma unroll
    for (int o = 16; o > 0; o >>= 1) sum += __shfl_xor_sync(0xffffffffu, sum, o);
    float ls = m + logf(sum);
    row[lane] = v0 - ls;
    if (lane < 8) row[lane + 32] = v1 - ls;
}

// ------------------------------------------------------------------------------
extern "C" void kernel_launch(void* const* d_in, const int* in_sizes, int n_in,
                              void* d_out, int out_size) {
    const float* x        = (const float*)d_in[0];
    const int*   ei       = (const int*)d_in[1];   // int32 OR int64 words; k_decode detects
    const float* W1       = (const float*)d_in[2];
    const float* attS1    = (const float*)d_in[3];
    const float* attD1    = (const float*)d_in[4];
    const float* b1       = (const float*)d_in[5];
    const float* W2       = (const float*)d_in[6];
    const float* attS2    = (const float*)d_in[7];
    const float* attD2    = (const float*)d_in[8];
    const float* b2       = (const float*)d_in[9];
    float* out = (float*)d_out;

    int E = in_sizes[1] / 2;          // 1,600,000 (element count of edge_index / 2)
    if (E > EMAX) E = EMAX;
    int ET = E + NN;                   // with self loops

    k_decode<<<(ET + 255) / 256, 256>>>(ei, E);
    k_zero<<<4096, 256>>>(out);
    k_gemm1<<<(NN + 63) / 64, 256>>>(x, W1);
    k_a1<<<(NN + 255) / 256, 256>>>(attS1, attD1);
    k_e1den<<<(ET + 255) / 256, 256>>>(ET);
    {
        long long lanes = (long long)ET * 16;
        int blocks = (int)((lanes + 255) / 256);
        k_e1scat<<<blocks, 256>>>(ET);
    }
    k_l2<<<(NN + 127) / 128, 128>>>(W2, b1, attS2, attD2);
    k_e2den<<<(ET + 255) / 256, 256>>>(ET);
    {
        long long lanes = (long long)ET * 16;
        int blocks = (int)((lanes + 255) / 256);
        k_e2scat<<<blocks, 256>>>(ET, out);
    }
    k_lsm<<<(NN * 32 + 255) / 256, 256>>>(out, b2);
}